// round 4
// baseline (speedup 1.0000x reference)
#include <cuda_runtime.h>
#include <math.h>

#define TT   512
#define BB   64
#define HH   512
#define GG   2048   // 4*HH
#define EE   512
#define NCTA 128
#define UPC  4      // h-units per CTA  (HH / NCTA)
#define RPC  16     // gate rows per CTA (4 * UPC)
#define HB   (HH * BB)

typedef unsigned long long u64;

// ---------------- packed fp32x2 helpers (sm_103a FFMA2) ----------------
__device__ __forceinline__ u64 pack2(float lo, float hi) {
    u64 r; asm("mov.b64 %0,{%1,%2};" : "=l"(r) : "f"(lo), "f"(hi)); return r;
}
__device__ __forceinline__ void ffma2(u64 &d, u64 a, u64 b) {
    asm("fma.rn.f32x2 %0,%1,%2,%0;" : "+l"(d) : "l"(a), "l"(b));
}
__device__ __forceinline__ u64 fadd2(u64 a, u64 b) {
    u64 r; asm("add.rn.f32x2 %0,%1,%2;" : "=l"(r) : "l"(a), "l"(b)); return r;
}

// ---------------- scratch (device globals) ----------------
__device__ float g_x0[(size_t)TT * EE * BB];   // embedded input,  [T][E][B]
__device__ float g_xw[(size_t)TT * GG * BB];   // xW + bias,       [T][G][B]
__device__ float g_y0[(size_t)TT * HH * BB];   // layer0 outputs,  [T][H][B]
__device__ float g_y1[(size_t)TT * HH * BB];   // layer1 outputs,  [T][H][B]
__device__ float g_hbuf[2 * HB];               // double-buffered h, [2][H][B]
__device__ unsigned g_bar;                     // grid barrier counter

// ---------------- grid barrier (128 co-resident CTAs, wrap-safe) ----------------
__device__ __forceinline__ void grid_sync() {
    __syncthreads();
    if (threadIdx.x == 0) {
        __threadfence();
        unsigned ticket = atomicAdd(&g_bar, 1u);
        unsigned target = ticket - (ticket & (NCTA - 1)) + NCTA;
        while ((int)(*(volatile unsigned*)&g_bar - target) < 0) { }
        __threadfence();
    }
    __syncthreads();
}

// ---------------- embedding gather ----------------
__global__ void embed_kernel(const int* __restrict__ src,
                             const float* __restrict__ emb) {
    size_t idx = (size_t)blockIdx.x * blockDim.x + threadIdx.x;
    if (idx >= (size_t)TT * EE * BB) return;
    int b = (int)(idx & 63);
    int e = (int)((idx >> 6) & (EE - 1));
    int t = (int)(idx >> 15);
    g_x0[idx] = emb[(size_t)src[t * BB + b] * EE + e];
}

// ---------------- GEMM: C[t][col][b] = sum_k A[t][k][b]*W[col][k] + bias ----------------
// Block 256 thr = 8 warps. Warp: 16 cols x 64 batches (lane = 2 batches, f32x2).
// W staged transposed in smem [kk][col] (uniform float4 reads). A via LDG.64 (L1 hits).
__global__ void __launch_bounds__(256) gemm_xw_kernel(const float* __restrict__ W,
                                                      const float* __restrict__ b1,
                                                      const float* __restrict__ b2,
                                                      int layer) {
    const float* __restrict__ A = layer ? g_y0 : g_x0;
    float* __restrict__ C = g_xw;

    __shared__ float sWt[64][128];   // [kk][col] for current k-chunk (32 KB)

    const int tid  = threadIdx.x;
    const int t    = blockIdx.y;
    const int n0   = blockIdx.x * 128;
    const int wid  = tid >> 5;
    const int lane = tid & 31;
    const int c0   = wid * 16;
    const int lcol = tid & 127;       // fill: column
    const int lkh  = tid >> 7;        // fill: k half (0/1)

    u64 acc[16];
    #pragma unroll
    for (int r = 0; r < 16; ++r) acc[r] = 0ull;

    for (int kc = 0; kc < 512; kc += 64) {
        __syncthreads();
        // fill W tile transposed: sWt[kk][col]
        const float* wrow = W + (size_t)(n0 + lcol) * 512 + kc + lkh * 32;
        #pragma unroll
        for (int i = 0; i < 8; ++i) {
            float4 w4 = *(const float4*)(wrow + i * 4);
            int kk = lkh * 32 + i * 4;
            sWt[kk + 0][lcol] = w4.x;
            sWt[kk + 1][lcol] = w4.y;
            sWt[kk + 2][lcol] = w4.z;
            sWt[kk + 3][lcol] = w4.w;
        }
        __syncthreads();

        const u64* ap = (const u64*)(A + ((size_t)t * 512 + kc) * 64) + lane;
        #pragma unroll 8
        for (int kk = 0; kk < 64; ++kk) {
            u64 a = ap[(size_t)kk * 32];
            float4 w0 = *(const float4*)&sWt[kk][c0];
            float4 w1 = *(const float4*)&sWt[kk][c0 + 4];
            float4 w2 = *(const float4*)&sWt[kk][c0 + 8];
            float4 w3 = *(const float4*)&sWt[kk][c0 + 12];
            float wv[16] = {w0.x, w0.y, w0.z, w0.w, w1.x, w1.y, w1.z, w1.w,
                            w2.x, w2.y, w2.z, w2.w, w3.x, w3.y, w3.z, w3.w};
            #pragma unroll
            for (int r = 0; r < 16; ++r)
                ffma2(acc[r], a, pack2(wv[r], wv[r]));
        }
    }

    #pragma unroll
    for (int r = 0; r < 16; ++r) {
        int col = n0 + c0 + r;
        float bias = b1[col] + b2[col];
        u64 v = fadd2(acc[r], pack2(bias, bias));
        *((u64*)(C + ((size_t)t * GG + col) * BB) + lane) = v;
    }
}

// ---------------- persistent LSTM recurrence ----------------
// 128 CTAs x 256 threads. CTA owns 16 gate rows (4 h-units).
// Warp = k-slice of 64 (8 warps); lane = 2 batches; all 16 rows per warp.
// h read directly from gmem (L2) per step -- no smem staging.
__global__ void __launch_bounds__(256, 1) lstm_rec_kernel(const float* __restrict__ Whh,
                                                          int layer) {
    extern __shared__ float smem[];
    float* sWt = smem;                    // [512][16]  = 8192 floats (32 KB)
    float* sP  = sWt + 512 * 16;          // [8][16][64]= 8192 floats (32 KB)
    float* sC  = sP + 8 * 16 * 64;        // [4][64]    = 256 floats

    const float* __restrict__ xw = g_xw;
    float* __restrict__ y = layer ? g_y1 : g_y0;
    float* hbuf = g_hbuf;

    const int tid = threadIdx.x;
    const int cta = blockIdx.x;
    const int u0  = cta * UPC;

    // Load Whh slice transposed: sWt[k][r], local row r=q*4+j <-> global row q*HH+u0+j
    {
        const int r = tid >> 4;            // 16 rows, 16 threads each
        const int q = r >> 2, j = r & 3;
        const float* srcw = Whh + (size_t)(q * HH + u0 + j) * HH;
        #pragma unroll
        for (int c = 0; c < 8; ++c) {
            int k = c * 64 + (tid & 15) * 4;
            float4 w = *(const float4*)(srcw + k);
            sWt[(k + 0) * 16 + r] = w.x;
            sWt[(k + 1) * 16 + r] = w.y;
            sWt[(k + 2) * 16 + r] = w.z;
            sWt[(k + 3) * 16 + r] = w.w;
        }
    }
    for (int i = tid; i < UPC * BB; i += 256) sC[i] = 0.f;
    for (int i = tid; i < UPC * BB; i += 256) hbuf[u0 * BB + i] = 0.f;
    grid_sync();

    const int ksl  = tid >> 5;     // warp = k-slice
    const int lane = tid & 31;
    // gate-phase mapping
    const int bb = tid & 63, jj = tid >> 6;

    int cur = 0;
    for (int t = 0; t < TT; ++t) {
        // ---- dot: acc[r] += h[k][b2..b2+1] * W[r][k] over this warp's k-slice ----
        u64 acc[16];
        #pragma unroll
        for (int r = 0; r < 16; ++r) acc[r] = 0ull;

        const u64* hp = (const u64*)(hbuf + cur * HB + ksl * 64 * BB) + lane;
        const float* wp = sWt + (ksl * 64) * 16;
        #pragma unroll 4
        for (int kk = 0; kk < 64; ++kk) {
            u64 h2 = __ldcg(hp + (size_t)kk * 32);
            const float* wk = wp + kk * 16;
            float4 w0 = *(const float4*)(wk);
            float4 w1 = *(const float4*)(wk + 4);
            float4 w2 = *(const float4*)(wk + 8);
            float4 w3 = *(const float4*)(wk + 12);
            float wv[16] = {w0.x, w0.y, w0.z, w0.w, w1.x, w1.y, w1.z, w1.w,
                            w2.x, w2.y, w2.z, w2.w, w3.x, w3.y, w3.z, w3.w};
            #pragma unroll
            for (int r = 0; r < 16; ++r)
                ffma2(acc[r], h2, pack2(wv[r], wv[r]));
        }
        // store partials: sP[ksl][r][lane*2..+1]
        {
            u64* pp = (u64*)(sP + (ksl * 16) * 64) + lane;
            #pragma unroll
            for (int r = 0; r < 16; ++r) pp[r * 32] = acc[r];
        }
        __syncthreads();

        // ---- gates: thread = (jj unit, bb batch) ----
        {
            float gv4[4];
            #pragma unroll
            for (int q = 0; q < 4; ++q) {
                int col = q * HH + u0 + jj;
                int r   = q * 4 + jj;
                float v = __ldg(xw + ((size_t)t * GG + col) * BB + bb);
                #pragma unroll
                for (int s = 0; s < 8; ++s)
                    v += sP[(s * 16 + r) * 64 + bb];
                gv4[q] = v;
            }
            float iv = 1.f / (1.f + __expf(-gv4[0]));
            float fv = 1.f / (1.f + __expf(-gv4[1]));
            float gv = tanhf(gv4[2]);
            float ov = 1.f / (1.f + __expf(-gv4[3]));
            float c = fv * sC[jj * BB + bb] + iv * gv;
            sC[jj * BB + bb] = c;
            float h = ov * tanhf(c);
            hbuf[(cur ^ 1) * HB + (u0 + jj) * BB + bb] = h;
            y[((size_t)t * HH + (u0 + jj)) * BB + bb] = h;
        }
        grid_sync();
        cur ^= 1;
    }
}

// ---------------- output gather ----------------
__global__ void out_kernel(const int* __restrict__ sen_len, float* __restrict__ out) {
    int idx = blockIdx.x * blockDim.x + threadIdx.x;
    if (idx >= BB * HH) return;
    int b = idx >> 9;
    int u = idx & (HH - 1);
    int t = sen_len[b] - 1;
    out[idx] = g_y1[((size_t)t * HH + u) * BB + b];
}

// ---------------- launch ----------------
static const int REC_SMEM = (512 * 16 + 8 * 16 * 64 + UPC * BB) * (int)sizeof(float); // 66560

extern "C" void kernel_launch(void* const* d_in, const int* in_sizes, int n_in,
                              void* d_out, int out_size) {
    const int*   src     = (const int*)d_in[0];
    const int*   sen_len = (const int*)d_in[1];
    const float* emb     = (const float*)d_in[2];
    const float* Wih0    = (const float*)d_in[3];
    const float* Whh0    = (const float*)d_in[4];
    const float* bih0    = (const float*)d_in[5];
    const float* bhh0    = (const float*)d_in[6];
    const float* Wih1    = (const float*)d_in[7];
    const float* Whh1    = (const float*)d_in[8];
    const float* bih1    = (const float*)d_in[9];
    const float* bhh1    = (const float*)d_in[10];
    float* out = (float*)d_out;

    cudaFuncSetAttribute(lstm_rec_kernel,
                         cudaFuncAttributeMaxDynamicSharedMemorySize, REC_SMEM);

    embed_kernel<<<(TT * EE * BB + 255) / 256, 256>>>(src, emb);

    dim3 ggrid(GG / 128, TT);
    gemm_xw_kernel<<<ggrid, 256>>>(Wih0, bih0, bhh0, 0);
    lstm_rec_kernel<<<NCTA, 256, REC_SMEM>>>(Whh0, 0);

    gemm_xw_kernel<<<ggrid, 256>>>(Wih1, bih1, bhh1, 1);
    lstm_rec_kernel<<<NCTA, 256, REC_SMEM>>>(Whh1, 1);

    out_kernel<<<(BB * HH + 255) / 256, 256>>>(sen_len, out);
}